// round 4
// baseline (speedup 1.0000x reference)
#include <cuda_runtime.h>
#include <cstdint>

// ---------------------------------------------------------------------------
// VQ-VAE EMA quantizer: raw TF32 mma.sync GEMM + certified interval argmin.
//   lo_k = (p_k - c_k*G) + q_k*(dot~ + h_r)  is a lower bound of true v_k.
//   If 2nd-smallest lo > m1 + 2*c_{k1}*G  ->  k1 provably exact argmin.
//   Ambiguous rows (expected ~0) fixed exactly by vq_fix.
// ---------------------------------------------------------------------------

#define BB 131072
#define DD 128
#define KK 1024
#define BM 256
#define BN 64
#define NITER (KK/BN)   // 16
#define FCAP 8192
#define CBOUND 2.2e-3f

// smem byte offsets
#define SM_A    0         // 128KB x_hi tf32, A-frag permuted (+kc XOR swizzle)
#define SM_B    131072    // 2 stages x 32KB e_hi tf32, B-frag permuted
#define SM_P    196608    // 4KB p'_k = p_k - c_k*G
#define SM_Q    200704    // 4KB q_k
#define SM_C    204800    // 4KB c_k
#define SM_XX   208896    // 1KB h_r
#define SM_M1   209920    // 1KB
#define SM_K1   210944    // 1KB
#define SM_M2   211968    // 1KB
#define SM_RED  212992    // 64B
#define SMEM_BYTES 213056

__device__ float g_loss;
__device__ int   g_nflag;
__device__ int   g_flags[FCAP];
__device__ float g_p[KK];
__device__ float g_q[KK];
__device__ float g_c[KK];
__device__ float g_eb[KK * DD];   // B-frag permuted tf32 codebook (64-row tiles)

__device__ __forceinline__ float tf32r(float x) {
    uint32_t u;
    asm("cvt.rna.tf32.f32 %0, %1;" : "=r"(u) : "f"(x));
    return __uint_as_float(u);
}
__device__ __forceinline__ void mma_t(float c[4], const uint4& a, uint32_t b0, uint32_t b1) {
    asm volatile(
        "mma.sync.aligned.m16n8k8.row.col.f32.tf32.tf32.f32 "
        "{%0,%1,%2,%3},{%4,%5,%6,%7},{%8,%9},{%0,%1,%2,%3};"
        : "+f"(c[0]), "+f"(c[1]), "+f"(c[2]), "+f"(c[3])
        : "r"(a.x), "r"(a.y), "r"(a.z), "r"(a.w), "r"(b0), "r"(b1));
}
__device__ __forceinline__ void cp16(uint32_t dst_smem, const void* src) {
    asm volatile("cp.async.cg.shared.global [%0], [%1], 16;"
                 :: "r"(dst_smem), "l"(src) : "memory");
}
__device__ __forceinline__ uint32_t smem_u32(const void* p) {
    uint32_t a;
    asm("{ .reg .u64 t; cvta.to.shared.u64 t, %1; cvt.u32.u64 %0, t; }"
        : "=r"(a) : "l"(p));
    return a;
}

// ---------------------------------------------------------------------------
// prep: permuted tf32 codebook, p/q/c params, reset accumulators.
// one warp per codeword; B-tile = 64 codewords (32KB, frag layout).
// ---------------------------------------------------------------------------
__global__ void vq_prep(const float* __restrict__ E, const float* __restrict__ S) {
    int wid = threadIdx.x >> 5, lane = threadIdx.x & 31;
    int k = blockIdx.x * 8 + wid;
    float4 v = ((const float4*)(E + (size_t)k * DD))[lane];
    float s2 = v.x * v.x + v.y * v.y + v.z * v.z + v.w * v.w;
    #pragma unroll
    for (int o = 16; o > 0; o >>= 1) s2 += __shfl_xor_sync(0xffffffffu, s2, o);

    float hi[4] = {tf32r(v.x), tf32r(v.y), tf32r(v.z), tf32r(v.w)};

    int t = k >> 6, n = k & 63;
    int np = n >> 4, nb = n & 15, sub = nb >> 3, nn = nb & 7;
    int d0 = lane * 4;
    int kc = d0 >> 3;
    int regbase = (lane & 1) + 2 * sub;   // (kk>>2) + 2*sub
    #pragma unroll
    for (int j = 0; j < 4; ++j) {
        int ls = nn * 4 + j;
        g_eb[(size_t)t * 8192 + (size_t)((kc * 4 + np) * 32 + ls) * 4 + regbase] = hi[j];
    }
    if (lane == 0) {
        float s = S[k];
        g_p[k] = s * s2;
        g_q[k] = -2.0f * s;
        g_c[k] = CBOUND * s * sqrtf(s2);
    }
    if (blockIdx.x == 0 && threadIdx.x == 0) { g_loss = 0.0f; g_nflag = 0; }
}

// ---------------------------------------------------------------------------
// main: 256 rows/CTA vs full codebook, BN=64 per iter, warps 4M x 2N.
// ---------------------------------------------------------------------------
__global__ __launch_bounds__(256, 1) void vq_main(
    const float* __restrict__ X, const float* __restrict__ E,
    float* __restrict__ out, int out_size)
{
    extern __shared__ char smem[];
    const uint32_t sb = smem_u32(smem);
    const int tid    = threadIdx.x;
    const int lane   = tid & 31;
    const int wid    = tid >> 5;
    const int warp_m = wid >> 1;
    const int warp_n = wid & 1;
    const int b0     = blockIdx.x * BM;

    float* ps = (float*)(smem + SM_P);
    float* qs = (float*)(smem + SM_Q);
    float* cs = (float*)(smem + SM_C);
    float* xx = (float*)(smem + SM_XX);
    float* red = (float*)(smem + SM_RED);

    // issue B tile 0 immediately (hides L2 latency behind prolog)
    {
        uint32_t dh = sb + SM_B + tid * 16;
        const char* src = (const char*)g_eb + tid * 16;
        #pragma unroll
        for (int r = 0; r < 8; ++r) cp16(dh + r * 4096, src + r * 4096);
        asm volatile("cp.async.commit_group;" ::: "memory");
    }

    // ---- X tile: load, tf32-round into A-frag layout (kc-XOR swizzled), norms, G ----
    float gmax = 0.0f;
    {
        const float4* Xg = (const float4*)(X + (size_t)b0 * DD);
        float* A = (float*)(smem + SM_A);
        #pragma unroll
        for (int it = 0; it < 32; ++it) {
            int idx = tid + it * 256;
            int r = idx >> 5;          // uniform per warp
            int d4 = idx & 31;         // == lane
            float4 v = Xg[r * 32 + d4];
            float n = v.x * v.x + v.y * v.y + v.z * v.z + v.w * v.w;
            #pragma unroll
            for (int o = 16; o > 0; o >>= 1) n += __shfl_xor_sync(0xffffffffu, n, o);
            if (lane == 0) xx[r] = -0.5f * n;
            gmax = fmaxf(gmax, n);
            int mt = r >> 4, rm = r & 15;
            int kc = d4 >> 1;
            int reg = (rm >> 3) + ((d4 & 1) << 1);
            float e[4] = {v.x, v.y, v.z, v.w};
            #pragma unroll
            for (int j = 0; j < 4; ++j) {
                int ls = ((rm & 7) * 4 + j) ^ (kc & 7);
                A[((kc * 16 + mt) * 32 + ls) * 4 + reg] = tf32r(e[j]);
            }
        }
    }
    if (lane == 0) red[wid] = gmax;
    __syncthreads();
    float G;
    {
        float g = red[0];
        #pragma unroll
        for (int w = 1; w < 8; ++w) g = fmaxf(g, red[w]);
        G = sqrtf(g) * 1.0001f;
    }
    // p' / q / c -> smem
    #pragma unroll
    for (int j = 0; j < 4; ++j) {
        int k = tid + 256 * j;
        float c = g_c[k];
        ps[k] = g_p[k] - c * G;
        qs[k] = g_q[k];
        cs[k] = c;
    }
    asm volatile("cp.async.wait_group 0;" ::: "memory");
    __syncthreads();

    // per-row h for this thread's 8 row-slots
    float hrow[8];
    #pragma unroll
    for (int mt = 0; mt < 4; ++mt)
        #pragma unroll
        for (int hf = 0; hf < 2; ++hf)
            hrow[mt * 2 + hf] = xx[warp_m * 64 + mt * 16 + (lane >> 2) + hf * 8];

    float m1[8], m2[8];
    int   k1[8];
    #pragma unroll
    for (int i = 0; i < 8; ++i) { m1[i] = 3.4e38f; m2[i] = 3.4e38f; k1[i] = 0; }

    const uint4* Abase = (const uint4*)(smem + SM_A);

    for (int t = 0; t < NITER; ++t) {
        const int stage = t & 1;
        if (t + 1 < NITER) {
            uint32_t dh = sb + SM_B + (stage ^ 1) * 32768 + tid * 16;
            const char* src = (const char*)g_eb + (size_t)(t + 1) * 32768 + tid * 16;
            #pragma unroll
            for (int r = 0; r < 8; ++r) cp16(dh + r * 4096, src + r * 4096);
            asm volatile("cp.async.commit_group;" ::: "memory");
        }

        const uint4* Bbase = (const uint4*)(smem + SM_B + stage * 32768);

        float acc[4][4][4];
        #pragma unroll
        for (int mt = 0; mt < 4; ++mt)
            #pragma unroll
            for (int nt = 0; nt < 4; ++nt)
                #pragma unroll
                for (int j = 0; j < 4; ++j) acc[mt][nt][j] = 0.0f;

        // register-pipelined frag loads
        uint4 a[2][4], b[2][2];
        #pragma unroll
        for (int mt = 0; mt < 4; ++mt)
            a[0][mt] = Abase[(warp_m * 4 + mt) * 32 + lane];
        b[0][0] = Bbase[(warp_n * 2) * 32 + lane];
        b[0][1] = Bbase[(warp_n * 2 + 1) * 32 + lane];

        #pragma unroll
        for (int kc = 0; kc < 16; ++kc) {
            const int cur = kc & 1, nxt = cur ^ 1;
            if (kc < 15) {
                int kn = kc + 1;
                #pragma unroll
                for (int mt = 0; mt < 4; ++mt)
                    a[nxt][mt] = Abase[(kn * 16 + warp_m * 4 + mt) * 32 + (lane ^ (kn & 7))];
                b[nxt][0] = Bbase[(kn * 4 + warp_n * 2) * 32 + lane];
                b[nxt][1] = Bbase[(kn * 4 + warp_n * 2 + 1) * 32 + lane];
            }
            #pragma unroll
            for (int mt = 0; mt < 4; ++mt) {
                mma_t(acc[mt][0], a[cur][mt], b[cur][0].x, b[cur][0].y);
                mma_t(acc[mt][1], a[cur][mt], b[cur][0].z, b[cur][0].w);
                mma_t(acc[mt][2], a[cur][mt], b[cur][1].x, b[cur][1].y);
                mma_t(acc[mt][3], a[cur][mt], b[cur][1].z, b[cur][1].w);
            }
        }

        // epilogue: certified lower bounds + top-2 tracking
        #pragma unroll
        for (int nt = 0; nt < 4; ++nt) {
            int k0 = t * 64 + warp_n * 32 + nt * 8 + ((lane & 3) << 1);
            float2 qq = *(const float2*)(qs + k0);
            float2 pp = *(const float2*)(ps + k0);
            #pragma unroll
            for (int mt = 0; mt < 4; ++mt) {
                #pragma unroll
                for (int hf = 0; hf < 2; ++hf) {
                    int rs = mt * 2 + hf;
                    float lo0 = fmaf(qq.x, acc[mt][nt][hf * 2 + 0] + hrow[rs], pp.x);
                    float lo1 = fmaf(qq.y, acc[mt][nt][hf * 2 + 1] + hrow[rs], pp.y);
                    m2[rs] = fminf(m2[rs], fmaxf(m1[rs], lo0));
                    if (lo0 < m1[rs]) { m1[rs] = lo0; k1[rs] = k0; }
                    m2[rs] = fminf(m2[rs], fmaxf(m1[rs], lo1));
                    if (lo1 < m1[rs]) { m1[rs] = lo1; k1[rs] = k0 + 1; }
                }
            }
        }

        asm volatile("cp.async.wait_group 0;" ::: "memory");
        __syncthreads();
    }

    // ---- reduce: lanes sharing rows (xor 1,2), then warp_n pair via smem ----
    #pragma unroll
    for (int o = 1; o <= 2; o <<= 1) {
        #pragma unroll
        for (int rs = 0; rs < 8; ++rs) {
            float ov = __shfl_xor_sync(0xffffffffu, m1[rs], o);
            int   ok = __shfl_xor_sync(0xffffffffu, k1[rs], o);
            float o2 = __shfl_xor_sync(0xffffffffu, m2[rs], o);
            m2[rs] = fminf(fminf(m2[rs], o2), fmaxf(m1[rs], ov));
            if (ov < m1[rs] || (ov == m1[rs] && ok < k1[rs])) { m1[rs] = ov; k1[rs] = ok; }
        }
    }
    float* sm1 = (float*)(smem + SM_M1);
    int*   sk1 = (int*)(smem + SM_K1);
    float* sm2 = (float*)(smem + SM_M2);
    if (warp_n == 0 && (lane & 3) == 0) {
        #pragma unroll
        for (int rs = 0; rs < 8; ++rs) {
            int row = warp_m * 64 + (rs >> 1) * 16 + (lane >> 2) + (rs & 1) * 8;
            sm1[row] = m1[rs]; sk1[row] = k1[rs]; sm2[row] = m2[rs];
        }
    }
    __syncthreads();
    if (warp_n == 1 && (lane & 3) == 0) {
        #pragma unroll
        for (int rs = 0; rs < 8; ++rs) {
            int row = warp_m * 64 + (rs >> 1) * 16 + (lane >> 2) + (rs & 1) * 8;
            float a1 = sm1[row]; int ak = sk1[row]; float a2 = sm2[row];
            float nm2 = fminf(fminf(a2, m2[rs]), fmaxf(a1, m1[rs]));
            float nm1 = a1; int nk = ak;
            if (m1[rs] < a1 || (m1[rs] == a1 && k1[rs] < ak)) { nm1 = m1[rs]; nk = k1[rs]; }
            sm1[row] = nm1; sk1[row] = nk; sm2[row] = nm2;
        }
    }
    __syncthreads();

    // ---- per-row finalize: idx out, flag ambiguous, loss estimate ----
    const bool full = (out_size >= BB * DD + 1 + BB);
    float lsum;
    {
        int row = tid;
        float v1 = sm1[row], v2 = sm2[row];
        int   kk = sk1[row];
        float b1 = cs[kk] * G;
        if (full) out[(size_t)BB * DD + 1 + b0 + row] = (float)kk;
        if (v2 <= v1 + 2.1f * b1 && full) {
            int pos = atomicAdd(&g_nflag, 1);
            if (pos < FCAP) g_flags[pos] = b0 + row;
        }
        lsum = -2.0f * (v1 + b1) / qs[kk];   // dist^2 estimate (unbiased)
    }
    #pragma unroll
    for (int o = 16; o > 0; o >>= 1) lsum += __shfl_xor_sync(0xffffffffu, lsum, o);
    __syncthreads();   // sm arrays stable; red reuse
    if (lane == 0) red[wid] = lsum;
    __syncthreads();
    if (tid == 0) {
        float s = 0.0f;
        #pragma unroll
        for (int w = 0; w < 8; ++w) s += red[w];
        atomicAdd(&g_loss, s);
    }

    // ---- gather z_embed: warp w handles rows [w*32, w*32+32) ----
    {
        #pragma unroll 4
        for (int r2 = 0; r2 < 32; ++r2) {
            int row = wid * 32 + r2;
            int kk = sk1[row];
            float4 v = ((const float4*)(E + (size_t)kk * DD))[lane];
            ((float4*)(out + (size_t)(b0 + row) * DD))[lane] = v;
        }
    }
}

// ---------------------------------------------------------------------------
// fix: exact fp32 brute-force for ambiguous rows (expected ~0)
// ---------------------------------------------------------------------------
__global__ void vq_fix(const float* __restrict__ X, const float* __restrict__ E,
                       float* __restrict__ out, int out_size) {
    if (out_size < BB * DD + 1 + BB) return;
    __shared__ float xs[DD];
    __shared__ float vs[KK];
    int n = g_nflag;
    if (n > FCAP) n = FCAP;
    for (int i = 0; i < n; ++i) {
        int row = g_flags[i];
        if (threadIdx.x < DD) xs[threadIdx.x] = X[(size_t)row * DD + threadIdx.x];
        __syncthreads();
        float h = 0.0f;
        for (int d = 0; d < DD; ++d) h = fmaf(xs[d], xs[d], h);
        h = -0.5f * h;
        for (int j = 0; j < 4; ++j) {
            int k = threadIdx.x * 4 + j;
            const float* e = E + (size_t)k * DD;
            float dot = 0.0f;
            for (int d = 0; d < DD; ++d) dot = fmaf(xs[d], e[d], dot);
            vs[k] = g_p[k] + g_q[k] * (dot + h);
        }
        __syncthreads();
        if (threadIdx.x == 0) {
            float best = vs[0]; int bk = 0;
            for (int k = 1; k < KK; ++k) if (vs[k] < best) { best = vs[k]; bk = k; }
            int kold = (int)out[(size_t)BB * DD + 1 + row];
            if (bk != kold) {
                out[(size_t)BB * DD + 1 + row] = (float)bk;
                float dnew = -2.0f * vs[bk] / g_q[bk];
                float dold = -2.0f * vs[kold] / g_q[kold];
                atomicAdd(&g_loss, dnew - dold);
            }
        }
        __syncthreads();
        int bk = (int)out[(size_t)BB * DD + 1 + row];
        if (threadIdx.x < 32) {
            float4 v = ((const float4*)(E + (size_t)bk * DD))[threadIdx.x];
            ((float4*)(out + (size_t)row * DD))[threadIdx.x] = v;
        }
        __syncthreads();
    }
}

__global__ void vq_fin(float* __restrict__ out, int out_size) {
    if (out_size >= BB * DD + 1)
        out[BB * DD] = 0.25f * g_loss / (float)((size_t)BB * DD);
}

extern "C" void kernel_launch(void* const* d_in, const int* in_sizes, int n_in,
                              void* d_out, int out_size) {
    const float* X = (const float*)d_in[0];
    const float* E = (const float*)d_in[1];
    const float* S = (const float*)d_in[2];
    float* out = (float*)d_out;

    cudaFuncSetAttribute(vq_main, cudaFuncAttributeMaxDynamicSharedMemorySize, SMEM_BYTES);

    vq_prep<<<KK / 8, 256>>>(E, S);
    vq_main<<<BB / BM, 256, SMEM_BYTES>>>(X, E, out, out_size);
    vq_fix<<<1, 256>>>(X, E, out, out_size);
    vq_fin<<<1, 1>>>(out, out_size);
}

// round 5
// speedup vs baseline: 4.3910x; 4.3910x over previous
#include <cuda_runtime.h>
#include <cstdint>

// ---------------------------------------------------------------------------
// VQ-VAE EMA quantizer: raw TF32 mma.sync + certified interval argmin.
//   lo_k = (p_k - c_k G) + q_k (dot~ + h_r)   <= true v_k <= lo_k + 2 c_k G
//   If m2 > m1 + 2 c_{k1} G (+slack)  ->  k1 provably the exact argmin.
//   Ambiguous rows (expected ~100) fixed exactly in parallel by vq_fix.
// ---------------------------------------------------------------------------

#define BB 131072
#define DD 128
#define KK 1024
#define BM 128
#define BN 32
#define NITER (KK/BN)   // 32
#define FCAP 16384
#define CBOUND 1.03e-3f

// smem byte offsets (per CTA; 2 CTAs/SM)
#define SM_A    0         // 64KB x tf32 A-frag permuted
#define SM_B    65536     // 2 stages x 16KB e tf32 B-frag permuted
#define SM_P    98304     // 4KB p'_k = p_k - c_k*G
#define SM_Q    102400    // 4KB q_k
#define SM_C    106496    // 4KB c_k
#define SM_XX   110592    // 512B h_r
#define SM_M1   111104    // 512B
#define SM_K1   111616    // 512B
#define SM_M2   112128    // 512B
#define SM_RED  112640    // 64B
#define SMEM_BYTES 112704

__device__ float g_loss;
__device__ int   g_nflag;
__device__ int   g_flags[FCAP];
__device__ float g_fest[FCAP];
__device__ float g_p[KK];
__device__ float g_q[KK];
__device__ float g_c[KK];
__device__ float g_eb[KK * DD];   // B-frag permuted tf32 codebook (32-row tiles)

__device__ __forceinline__ float tf32r(float x) {
    uint32_t u;
    asm("cvt.rna.tf32.f32 %0, %1;" : "=r"(u) : "f"(x));
    return __uint_as_float(u);
}
__device__ __forceinline__ void mma_t(float c[4], const uint4& a, uint32_t b0, uint32_t b1) {
    asm volatile(
        "mma.sync.aligned.m16n8k8.row.col.f32.tf32.tf32.f32 "
        "{%0,%1,%2,%3},{%4,%5,%6,%7},{%8,%9},{%0,%1,%2,%3};"
        : "+f"(c[0]), "+f"(c[1]), "+f"(c[2]), "+f"(c[3])
        : "r"(a.x), "r"(a.y), "r"(a.z), "r"(a.w), "r"(b0), "r"(b1));
}
__device__ __forceinline__ void cp16(uint32_t dst_smem, const void* src) {
    asm volatile("cp.async.cg.shared.global [%0], [%1], 16;"
                 :: "r"(dst_smem), "l"(src) : "memory");
}
__device__ __forceinline__ uint32_t smem_u32(const void* p) {
    uint32_t a;
    asm("{ .reg .u64 t; cvta.to.shared.u64 t, %1; cvt.u32.u64 %0, t; }"
        : "=r"(a) : "l"(p));
    return a;
}

// ---------------------------------------------------------------------------
// prep: tf32 codebook in B-frag layout (32-codeword tiles), p/q/c, resets.
// ---------------------------------------------------------------------------
__global__ void vq_prep(const float* __restrict__ E, const float* __restrict__ S) {
    int wid = threadIdx.x >> 5, lane = threadIdx.x & 31;
    int k = blockIdx.x * 8 + wid;
    float4 v = ((const float4*)(E + (size_t)k * DD))[lane];
    float s2 = v.x * v.x + v.y * v.y + v.z * v.z + v.w * v.w;
    #pragma unroll
    for (int o = 16; o > 0; o >>= 1) s2 += __shfl_xor_sync(0xffffffffu, s2, o);

    float hi[4] = {tf32r(v.x), tf32r(v.y), tf32r(v.z), tf32r(v.w)};

    int t = k >> 5, n = k & 31;
    int np = n >> 4, nb = n & 15, sub = nb >> 3, nn = nb & 7;
    int kc = lane >> 1;                       // (lane*4)/8
    int regbase = (lane & 1) + 2 * sub;
    #pragma unroll
    for (int j = 0; j < 4; ++j) {
        int ls = nn * 4 + j;
        g_eb[(size_t)t * 4096 + (size_t)((kc * 2 + np) * 32 + ls) * 4 + regbase] = hi[j];
    }
    if (lane == 0) {
        float s = S[k];
        g_p[k] = s * s2;
        g_q[k] = -2.0f * s;
        g_c[k] = CBOUND * s * sqrtf(s2);
    }
    if (blockIdx.x == 0 && threadIdx.x == 0) { g_loss = 0.0f; g_nflag = 0; }
}

// ---------------------------------------------------------------------------
// main: 128 rows/CTA vs full codebook; warps 4M x 2N; reg-pipelined frags.
// ---------------------------------------------------------------------------
__global__ __launch_bounds__(256, 2) void vq_main(
    const float* __restrict__ X, const float* __restrict__ E,
    float* __restrict__ out, int out_size)
{
    extern __shared__ char smem[];
    const uint32_t sb = smem_u32(smem);
    const int tid    = threadIdx.x;
    const int lane   = tid & 31;
    const int wid    = tid >> 5;
    const int warp_m = wid >> 1;
    const int warp_n = wid & 1;
    const int b0     = blockIdx.x * BM;

    float* ps  = (float*)(smem + SM_P);
    float* qs  = (float*)(smem + SM_Q);
    float* cs  = (float*)(smem + SM_C);
    float* xx  = (float*)(smem + SM_XX);
    float* red = (float*)(smem + SM_RED);

    // B tile 0 fetch starts immediately
    {
        uint32_t dh = sb + SM_B + tid * 16;
        const char* src = (const char*)g_eb + tid * 16;
        #pragma unroll
        for (int r = 0; r < 4; ++r) cp16(dh + r * 4096, src + r * 4096);
        asm volatile("cp.async.commit_group;" ::: "memory");
    }

    // ---- X tile: load, tf32-round into A-frag layout, norms, G ----
    float gmax = 0.0f;
    {
        const float4* Xg = (const float4*)(X + (size_t)b0 * DD);
        float* A = (float*)(smem + SM_A);
        #pragma unroll
        for (int it = 0; it < 16; ++it) {
            int idx = tid + it * 256;
            int r = idx >> 5;          // uniform per warp
            int d4 = idx & 31;
            float4 v = Xg[r * 32 + d4];
            float n = v.x * v.x + v.y * v.y + v.z * v.z + v.w * v.w;
            #pragma unroll
            for (int o = 16; o > 0; o >>= 1) n += __shfl_xor_sync(0xffffffffu, n, o);
            if (lane == 0) xx[r] = -0.5f * n;
            gmax = fmaxf(gmax, n);
            int mt = r >> 4, rm = r & 15;
            int kc = d4 >> 1;
            int reg = (rm >> 3) + ((d4 & 1) << 1);
            int base = ((kc * 8 + mt) * 32) * 4 + reg;
            float e[4] = {v.x, v.y, v.z, v.w};
            #pragma unroll
            for (int j = 0; j < 4; ++j)
                A[base + ((rm & 7) * 4 + j) * 4] = tf32r(e[j]);
        }
    }
    if (lane == 0) red[wid] = gmax;
    __syncthreads();
    float G;
    {
        float g = red[0];
        #pragma unroll
        for (int w = 1; w < 8; ++w) g = fmaxf(g, red[w]);
        G = sqrtf(g) * 1.0001f;
    }
    #pragma unroll
    for (int j = 0; j < 4; ++j) {
        int k = tid + 256 * j;
        float c = g_c[k];
        ps[k] = g_p[k] - c * G;
        qs[k] = g_q[k];
        cs[k] = c;
    }
    asm volatile("cp.async.wait_group 0;" ::: "memory");
    __syncthreads();

    // h per row-slot (rs = mt*2+pr)
    float hrow[4];
    #pragma unroll
    for (int mt = 0; mt < 2; ++mt)
        #pragma unroll
        for (int pr = 0; pr < 2; ++pr)
            hrow[mt * 2 + pr] = xx[warp_m * 32 + mt * 16 + (lane >> 2) + 8 * pr];

    float m1v[4] = {3.4e38f, 3.4e38f, 3.4e38f, 3.4e38f};
    float m2v[4] = {3.4e38f, 3.4e38f, 3.4e38f, 3.4e38f};
    int   k1i[4] = {0, 0, 0, 0};

    const uint4* Ah = (const uint4*)(smem + SM_A) + warp_m * 64 + lane;

    for (int t = 0; t < NITER; ++t) {
        const int stage = t & 1;
        if (t + 1 < NITER) {
            uint32_t dh = sb + SM_B + (stage ^ 1) * 16384 + tid * 16;
            const char* src = (const char*)g_eb + (size_t)(t + 1) * 16384 + tid * 16;
            #pragma unroll
            for (int r = 0; r < 4; ++r) cp16(dh + r * 4096, src + r * 4096);
            asm volatile("cp.async.commit_group;" ::: "memory");
        }

        const uint4* Bh = (const uint4*)(smem + SM_B + stage * 16384) + warp_n * 32 + lane;

        float acc[2][2][4];
        #pragma unroll
        for (int mt = 0; mt < 2; ++mt)
            #pragma unroll
            for (int nt = 0; nt < 2; ++nt)
                #pragma unroll
                for (int j = 0; j < 4; ++j) acc[mt][nt][j] = 0.0f;

        // register-pipelined mainloop
        uint4 a0 = Ah[0], a1 = Ah[32], bb = Bh[0];
        #pragma unroll
        for (int kc = 0; kc < 16; ++kc) {
            uint4 a0n, a1n, bn;
            if (kc < 15) {
                a0n = Ah[(kc + 1) * 256];
                a1n = Ah[(kc + 1) * 256 + 32];
                bn  = Bh[(kc + 1) * 64];
            }
            mma_t(acc[0][0], a0, bb.x, bb.y);
            mma_t(acc[0][1], a0, bb.z, bb.w);
            mma_t(acc[1][0], a1, bb.x, bb.y);
            mma_t(acc[1][1], a1, bb.z, bb.w);
            if (kc < 15) { a0 = a0n; a1 = a1n; bb = bn; }
        }

        // epilogue: certified lower bounds + top-2 tracking
        #pragma unroll
        for (int nt = 0; nt < 2; ++nt) {
            int k0 = t * 32 + warp_n * 16 + nt * 8 + ((lane & 3) << 1);
            float p0 = ps[k0], p1 = ps[k0 + 1];
            float q0 = qs[k0], q1 = qs[k0 + 1];
            #pragma unroll
            for (int mt = 0; mt < 2; ++mt) {
                #pragma unroll
                for (int pr = 0; pr < 2; ++pr) {
                    int rs = mt * 2 + pr;
                    float lo0 = fmaf(q0, acc[mt][nt][pr * 2 + 0] + hrow[rs], p0);
                    float lo1 = fmaf(q1, acc[mt][nt][pr * 2 + 1] + hrow[rs], p1);
                    m2v[rs] = fminf(m2v[rs], fmaxf(m1v[rs], lo0));
                    if (lo0 < m1v[rs]) { m1v[rs] = lo0; k1i[rs] = k0; }
                    m2v[rs] = fminf(m2v[rs], fmaxf(m1v[rs], lo1));
                    if (lo1 < m1v[rs]) { m1v[rs] = lo1; k1i[rs] = k0 + 1; }
                }
            }
        }

        asm volatile("cp.async.wait_group 0;" ::: "memory");
        __syncthreads();
    }

    // ---- reduce: lanes sharing rows (xor 1,2), then warp_n pair via smem ----
    #pragma unroll
    for (int o = 1; o <= 2; o <<= 1) {
        #pragma unroll
        for (int rs = 0; rs < 4; ++rs) {
            float ov = __shfl_xor_sync(0xffffffffu, m1v[rs], o);
            int   ok = __shfl_xor_sync(0xffffffffu, k1i[rs], o);
            float o2 = __shfl_xor_sync(0xffffffffu, m2v[rs], o);
            m2v[rs] = fminf(fminf(m2v[rs], o2), fmaxf(m1v[rs], ov));
            if (ov < m1v[rs] || (ov == m1v[rs] && ok < k1i[rs])) { m1v[rs] = ov; k1i[rs] = ok; }
        }
    }
    float* sm1 = (float*)(smem + SM_M1);
    int*   sk1 = (int*)(smem + SM_K1);
    float* sm2 = (float*)(smem + SM_M2);
    if (warp_n == 0 && (lane & 3) == 0) {
        #pragma unroll
        for (int rs = 0; rs < 4; ++rs) {
            int row = warp_m * 32 + (rs >> 1) * 16 + (lane >> 2) + (rs & 1) * 8;
            sm1[row] = m1v[rs]; sk1[row] = k1i[rs]; sm2[row] = m2v[rs];
        }
    }
    __syncthreads();
    if (warp_n == 1 && (lane & 3) == 0) {
        #pragma unroll
        for (int rs = 0; rs < 4; ++rs) {
            int row = warp_m * 32 + (rs >> 1) * 16 + (lane >> 2) + (rs & 1) * 8;
            float a1 = sm1[row]; int ak = sk1[row]; float a2 = sm2[row];
            float nm2 = fminf(fminf(a2, m2v[rs]), fmaxf(a1, m1v[rs]));
            float nm1 = a1; int nk = ak;
            if (m1v[rs] < a1 || (m1v[rs] == a1 && k1i[rs] < ak)) { nm1 = m1v[rs]; nk = k1i[rs]; }
            sm1[row] = nm1; sk1[row] = nk; sm2[row] = nm2;
        }
    }
    __syncthreads();

    // ---- per-row finalize ----
    const bool full = (out_size >= BB * DD + 1 + BB);
    float lsum = 0.0f;
    if (tid < BM) {
        float v1 = sm1[tid], v2 = sm2[tid];
        int   kk = sk1[tid];
        float b1 = cs[kk] * G;
        if (full) out[(size_t)BB * DD + 1 + b0 + tid] = (float)kk;
        float est = -2.0f * (v1 + b1) / qs[kk];
        if (v2 <= v1 + 2.05f * b1 + 1e-4f && full) {
            int pos = atomicAdd(&g_nflag, 1);
            if (pos < FCAP) { g_flags[pos] = b0 + tid; g_fest[pos] = est; }
        }
        lsum = est;
    }
    #pragma unroll
    for (int o = 16; o > 0; o >>= 1) lsum += __shfl_xor_sync(0xffffffffu, lsum, o);
    __syncthreads();
    if (wid < 4 && lane == 0) red[wid] = lsum;
    __syncthreads();
    if (tid == 0) atomicAdd(&g_loss, red[0] + red[1] + red[2] + red[3]);

    // ---- gather z_embed ----
    {
        int r = tid >> 1, hf = tid & 1;
        int idx = sk1[r];
        const float4* Eq = (const float4*)(E + (size_t)idx * DD) + hf * 16;
        float4* Oq = (float4*)(out + (size_t)(b0 + r) * DD) + hf * 16;
        #pragma unroll
        for (int j = 0; j < 16; ++j) Oq[j] = Eq[j];
    }
}

// ---------------------------------------------------------------------------
// fix: exact fp32 argmin for flagged rows, one block per row (parallel).
// ---------------------------------------------------------------------------
__global__ void vq_fix(const float* __restrict__ X, const float* __restrict__ E,
                       float* __restrict__ out, int out_size) {
    if (out_size < BB * DD + 1 + BB) return;
    __shared__ float xs[DD];
    __shared__ float bv[256];
    __shared__ int   bi[256];
    int n = g_nflag;
    if (n > FCAP) n = FCAP;
    for (int i = blockIdx.x; i < n; i += gridDim.x) {
        int row = g_flags[i];
        if (threadIdx.x < DD) xs[threadIdx.x] = X[(size_t)row * DD + threadIdx.x];
        __syncthreads();
        float h = 0.0f;
        #pragma unroll 8
        for (int d = 0; d < DD; ++d) h = fmaf(xs[d], xs[d], h);
        h = -0.5f * h;
        float best = 3.4e38f; int bk = 0;
        #pragma unroll
        for (int j = 0; j < 4; ++j) {
            int k = threadIdx.x * 4 + j;
            const float* e = E + (size_t)k * DD;
            float dot = 0.0f;
            #pragma unroll 8
            for (int d = 0; d < DD; ++d) dot = fmaf(xs[d], e[d], dot);
            float v = g_p[k] + g_q[k] * (dot + h);
            if (v < best) { best = v; bk = k; }
        }
        bv[threadIdx.x] = best; bi[threadIdx.x] = bk;
        __syncthreads();
        for (int s = 128; s > 0; s >>= 1) {
            if (threadIdx.x < s) {
                float ov = bv[threadIdx.x + s]; int oi = bi[threadIdx.x + s];
                if (ov < bv[threadIdx.x] ||
                    (ov == bv[threadIdx.x] && oi < bi[threadIdx.x])) {
                    bv[threadIdx.x] = ov; bi[threadIdx.x] = oi;
                }
            }
            __syncthreads();
        }
        int kb = bi[0];
        if (threadIdx.x == 0) {
            out[(size_t)BB * DD + 1 + row] = (float)kb;
            float dexact = -2.0f * bv[0] / g_q[kb];
            atomicAdd(&g_loss, dexact - g_fest[i]);
        }
        if (threadIdx.x < 32) {
            float4 v = ((const float4*)(E + (size_t)kb * DD))[threadIdx.x];
            ((float4*)(out + (size_t)row * DD))[threadIdx.x] = v;
        }
        __syncthreads();
    }
}

__global__ void vq_fin(float* __restrict__ out, int out_size) {
    if (out_size >= BB * DD + 1)
        out[BB * DD] = 0.25f * g_loss / (float)((size_t)BB * DD);
}

extern "C" void kernel_launch(void* const* d_in, const int* in_sizes, int n_in,
                              void* d_out, int out_size) {
    const float* X = (const float*)d_in[0];
    const float* E = (const float*)d_in[1];
    const float* S = (const float*)d_in[2];
    float* out = (float*)d_out;

    cudaFuncSetAttribute(vq_main, cudaFuncAttributeMaxDynamicSharedMemorySize, SMEM_BYTES);

    vq_prep<<<KK / 8, 256>>>(E, S);
    vq_main<<<BB / BM, 256, SMEM_BYTES>>>(X, E, out, out_size);
    vq_fix<<<512, 256>>>(X, E, out, out_size);
    vq_fin<<<1, 1>>>(out, out_size);
}

// round 6
// speedup vs baseline: 11.4829x; 2.6151x over previous
#include <cuda_runtime.h>
#include <cuda_fp16.h>
#include <cstdint>

// ---------------------------------------------------------------------------
// VQ-VAE EMA quantizer: fp16 mma.sync (m16n8k16) + certified interval argmin.
//   lo_k = (p_k - c_k G) + q_k (dot~ + h_r)  <= true v_k <= lo_k + 2 c_k G
//   If m2 > m1 + 2 c_{k1} G (+slack)  ->  k1 provably the exact argmin.
//   Ambiguous rows (expected ~160) fixed exactly in parallel by vq_fix.
// ---------------------------------------------------------------------------

#define BB 131072
#define DD 128
#define KK 1024
#define BM 128
#define BN 64
#define NITER (KK/BN)   // 16
#define FCAP 16384
#define CBOUND 1.05e-3f

// smem byte offsets (per CTA; 2 CTAs/SM)
#define SM_A    0         // 32KB x fp16, A-frag permuted (+kc XOR swizzle)
#define SM_B    32768     // 2 stages x 16KB e fp16 B-frag permuted
#define SM_P    65536     // 4KB p'_k = p_k - c_k*G
#define SM_Q    69632     // 4KB q_k
#define SM_C    73728     // 4KB c_k
#define SM_XX   77824     // 512B h_r
#define SM_M1   78336     // 512B
#define SM_K1   78848     // 512B
#define SM_M2   79360     // 512B
#define SM_RED  79872     // 64B
#define SMEM_BYTES 79936

__device__ float g_loss;
__device__ int   g_nflag;
__device__ int   g_flags[FCAP];
__device__ float g_fest[FCAP];
__device__ float g_p[KK];
__device__ float g_q[KK];
__device__ float g_c[KK];
__device__ uint32_t g_eb[KK * DD / 2];   // B-frag permuted fp16 codebook (64-row tiles)

__device__ __forceinline__ void mma_h(float c[4], const uint4& a, uint32_t b0, uint32_t b1) {
    asm volatile(
        "mma.sync.aligned.m16n8k16.row.col.f32.f16.f16.f32 "
        "{%0,%1,%2,%3},{%4,%5,%6,%7},{%8,%9},{%0,%1,%2,%3};"
        : "+f"(c[0]), "+f"(c[1]), "+f"(c[2]), "+f"(c[3])
        : "r"(a.x), "r"(a.y), "r"(a.z), "r"(a.w), "r"(b0), "r"(b1));
}
__device__ __forceinline__ void cp16(uint32_t dst_smem, const void* src) {
    asm volatile("cp.async.cg.shared.global [%0], [%1], 16;"
                 :: "r"(dst_smem), "l"(src) : "memory");
}
__device__ __forceinline__ uint32_t smem_u32(const void* p) {
    uint32_t a;
    asm("{ .reg .u64 t; cvta.to.shared.u64 t, %1; cvt.u32.u64 %0, t; }"
        : "=r"(a) : "l"(p));
    return a;
}
__device__ __forceinline__ uint32_t h2pack(float lo, float hi) {
    __half2 h = __halves2half2(__float2half_rn(lo), __float2half_rn(hi));
    return *(uint32_t*)&h;
}

// ---------------------------------------------------------------------------
// prep: fp16 codebook in B-frag layout (64-codeword tiles), p/q/c, resets.
// one warp per codeword k.
// ---------------------------------------------------------------------------
__global__ void vq_prep(const float* __restrict__ E, const float* __restrict__ S) {
    int wid = threadIdx.x >> 5, lane = threadIdx.x & 31;
    int k = blockIdx.x * 8 + wid;
    float4 v = ((const float4*)(E + (size_t)k * DD))[lane];
    float s2 = v.x * v.x + v.y * v.y + v.z * v.z + v.w * v.w;
    #pragma unroll
    for (int o = 16; o > 0; o >>= 1) s2 += __shfl_xor_sync(0xffffffffu, s2, o);

    // B-frag layout: tile = 64 codewords (4096 b32 words).
    // uint4 idx = (kc*4+ng)*32 + (g*4+tl); b32 word = idx*4 + blocksel*2 + khi
    int t = k >> 6, n = k & 63;
    int ng = n >> 4, blocksel = (n >> 3) & 1, g = n & 7;
    float e[4] = {v.x, v.y, v.z, v.w};
    #pragma unroll
    for (int j2 = 0; j2 < 2; ++j2) {
        int d0 = 4 * lane + 2 * j2;
        int kc = d0 >> 4;
        int tl = (d0 & 7) >> 1;
        int khi = (d0 >> 3) & 1;
        uint32_t h = h2pack(e[2 * j2], e[2 * j2 + 1]);
        g_eb[(size_t)t * 4096 +
             (size_t)((kc * 4 + ng) * 32 + g * 4 + tl) * 4 + blocksel * 2 + khi] = h;
    }
    if (lane == 0) {
        float s = S[k];
        g_p[k] = s * s2;
        g_q[k] = -2.0f * s;
        g_c[k] = CBOUND * s * sqrtf(s2);
    }
    if (blockIdx.x == 0 && threadIdx.x == 0) { g_loss = 0.0f; g_nflag = 0; }
}

// ---------------------------------------------------------------------------
// main: 128 rows/CTA vs full codebook; BN=64/iter; warps 4M x 2N.
// ---------------------------------------------------------------------------
__global__ __launch_bounds__(256, 2) void vq_main(
    const float* __restrict__ X, const float* __restrict__ E,
    float* __restrict__ out, int out_size)
{
    extern __shared__ char smem[];
    const uint32_t sb = smem_u32(smem);
    const int tid    = threadIdx.x;
    const int lane   = tid & 31;
    const int wid    = tid >> 5;
    const int warp_m = wid >> 1;
    const int warp_n = wid & 1;
    const int b0     = blockIdx.x * BM;

    float* ps  = (float*)(smem + SM_P);
    float* qs  = (float*)(smem + SM_Q);
    float* cs  = (float*)(smem + SM_C);
    float* xx  = (float*)(smem + SM_XX);
    float* red = (float*)(smem + SM_RED);

    // B tile 0 fetch starts immediately
    {
        uint32_t dh = sb + SM_B + tid * 16;
        const char* src = (const char*)g_eb + tid * 16;
        #pragma unroll
        for (int r = 0; r < 4; ++r) cp16(dh + r * 4096, src + r * 4096);
        asm volatile("cp.async.commit_group;" ::: "memory");
    }

    // ---- X tile: load, fp16-round into A-frag layout (kc-XOR swizzle), norms, G ----
    float gmax = 0.0f;
    {
        const float4* Xg = (const float4*)(X + (size_t)b0 * DD);
        uint32_t* A32 = (uint32_t*)(smem + SM_A);
        #pragma unroll
        for (int it = 0; it < 16; ++it) {
            int idx = tid + it * 256;
            int r = idx >> 5;          // uniform per warp
            float4 v = Xg[r * 32 + lane];
            float n = v.x * v.x + v.y * v.y + v.z * v.z + v.w * v.w;
            #pragma unroll
            for (int o = 16; o > 0; o >>= 1) n += __shfl_xor_sync(0xffffffffu, n, o);
            if (lane == 0) xx[r] = -0.5f * n;
            gmax = fmaxf(gmax, n);
            int mtb = r >> 4, g = r & 7, rhigh = (r >> 3) & 1;
            int kc  = lane >> 2;
            int tl  = 2 * (lane & 1);
            int khi = (lane >> 1) & 1;
            int reg = rhigh + 2 * khi;
            int base = (kc * 8 + mtb) * 32;
            A32[(base + ((g * 4 + tl) ^ kc)) * 4 + reg]     = h2pack(v.x, v.y);
            A32[(base + ((g * 4 + tl + 1) ^ kc)) * 4 + reg] = h2pack(v.z, v.w);
        }
    }
    if (lane == 0) red[wid] = gmax;
    __syncthreads();
    float G;
    {
        float g = red[0];
        #pragma unroll
        for (int w = 1; w < 8; ++w) g = fmaxf(g, red[w]);
        G = sqrtf(g) * 1.0001f;
    }
    #pragma unroll
    for (int j = 0; j < 4; ++j) {
        int k = tid + 256 * j;
        float c = g_c[k];
        ps[k] = g_p[k] - c * G;
        qs[k] = g_q[k];
        cs[k] = c;
    }
    asm volatile("cp.async.wait_group 0;" ::: "memory");
    __syncthreads();

    // h per row-slot (rs = mt*2+pr): row = warp_m*32 + mt*16 + (lane>>2) + 8*pr
    float hrow[4];
    #pragma unroll
    for (int mt = 0; mt < 2; ++mt)
        #pragma unroll
        for (int pr = 0; pr < 2; ++pr)
            hrow[mt * 2 + pr] = xx[warp_m * 32 + mt * 16 + (lane >> 2) + 8 * pr];

    float m1v[4] = {3.4e38f, 3.4e38f, 3.4e38f, 3.4e38f};
    float m2v[4] = {3.4e38f, 3.4e38f, 3.4e38f, 3.4e38f};
    int   k1i[4] = {0, 0, 0, 0};

    const uint4* A4 = (const uint4*)(smem + SM_A);

    for (int t = 0; t < NITER; ++t) {
        const int stage = t & 1;
        if (t + 1 < NITER) {
            uint32_t dh = sb + SM_B + (stage ^ 1) * 16384 + tid * 16;
            const char* src = (const char*)g_eb + (size_t)(t + 1) * 16384 + tid * 16;
            #pragma unroll
            for (int r = 0; r < 4; ++r) cp16(dh + r * 4096, src + r * 4096);
            asm volatile("cp.async.commit_group;" ::: "memory");
        }

        const uint4* B4 = (const uint4*)(smem + SM_B + stage * 16384);

        float acc[2][4][4];
        #pragma unroll
        for (int mt = 0; mt < 2; ++mt)
            #pragma unroll
            for (int nb = 0; nb < 4; ++nb)
                #pragma unroll
                for (int j = 0; j < 4; ++j) acc[mt][nb][j] = 0.0f;

        // register-pipelined mainloop over kc (K=16 per step)
        uint4 a0 = A4[(warp_m * 2) * 32 + lane];
        uint4 a1 = A4[(warp_m * 2 + 1) * 32 + lane];
        uint4 bb0 = B4[(warp_n * 2) * 32 + lane];
        uint4 bb1 = B4[(warp_n * 2 + 1) * 32 + lane];
        #pragma unroll
        for (int kc = 0; kc < 8; ++kc) {
            uint4 a0n, a1n, b0n, b1n;
            if (kc < 7) {
                int kn = kc + 1;
                int ls = lane ^ kn;
                a0n = A4[(kn * 8 + warp_m * 2) * 32 + ls];
                a1n = A4[(kn * 8 + warp_m * 2 + 1) * 32 + ls];
                b0n = B4[(kn * 4 + warp_n * 2) * 32 + lane];
                b1n = B4[(kn * 4 + warp_n * 2 + 1) * 32 + lane];
            }
            mma_h(acc[0][0], a0, bb0.x, bb0.y);
            mma_h(acc[0][1], a0, bb0.z, bb0.w);
            mma_h(acc[0][2], a0, bb1.x, bb1.y);
            mma_h(acc[0][3], a0, bb1.z, bb1.w);
            mma_h(acc[1][0], a1, bb0.x, bb0.y);
            mma_h(acc[1][1], a1, bb0.z, bb0.w);
            mma_h(acc[1][2], a1, bb1.x, bb1.y);
            mma_h(acc[1][3], a1, bb1.z, bb1.w);
            if (kc < 7) { a0 = a0n; a1 = a1n; bb0 = b0n; bb1 = b1n; }
        }

        // epilogue: certified lower bounds + top-2 tracking (32 candidates)
        #pragma unroll
        for (int ntg = 0; ntg < 2; ++ntg) {
            #pragma unroll
            for (int blk = 0; blk < 2; ++blk) {
                int nb = ntg * 2 + blk;
                int k0 = t * 64 + (warp_n * 2 + ntg) * 16 + blk * 8 + ((lane & 3) << 1);
                float2 pp = *(const float2*)(ps + k0);
                float2 qq = *(const float2*)(qs + k0);
                #pragma unroll
                for (int mt = 0; mt < 2; ++mt) {
                    #pragma unroll
                    for (int pr = 0; pr < 2; ++pr) {
                        int rs = mt * 2 + pr;
                        float lo0 = fmaf(qq.x, acc[mt][nb][pr * 2 + 0] + hrow[rs], pp.x);
                        float lo1 = fmaf(qq.y, acc[mt][nb][pr * 2 + 1] + hrow[rs], pp.y);
                        m2v[rs] = fminf(m2v[rs], fmaxf(m1v[rs], lo0));
                        if (lo0 < m1v[rs]) { m1v[rs] = lo0; k1i[rs] = k0; }
                        m2v[rs] = fminf(m2v[rs], fmaxf(m1v[rs], lo1));
                        if (lo1 < m1v[rs]) { m1v[rs] = lo1; k1i[rs] = k0 + 1; }
                    }
                }
            }
        }

        asm volatile("cp.async.wait_group 0;" ::: "memory");
        __syncthreads();
    }

    // ---- reduce: lanes sharing rows (xor 1,2), then warp_n pair via smem ----
    #pragma unroll
    for (int o = 1; o <= 2; o <<= 1) {
        #pragma unroll
        for (int rs = 0; rs < 4; ++rs) {
            float ov = __shfl_xor_sync(0xffffffffu, m1v[rs], o);
            int   ok = __shfl_xor_sync(0xffffffffu, k1i[rs], o);
            float o2 = __shfl_xor_sync(0xffffffffu, m2v[rs], o);
            m2v[rs] = fminf(fminf(m2v[rs], o2), fmaxf(m1v[rs], ov));
            if (ov < m1v[rs] || (ov == m1v[rs] && ok < k1i[rs])) { m1v[rs] = ov; k1i[rs] = ok; }
        }
    }
    float* sm1 = (float*)(smem + SM_M1);
    int*   sk1 = (int*)(smem + SM_K1);
    float* sm2 = (float*)(smem + SM_M2);
    if (warp_n == 0 && (lane & 3) == 0) {
        #pragma unroll
        for (int rs = 0; rs < 4; ++rs) {
            int row = warp_m * 32 + (rs >> 1) * 16 + (lane >> 2) + (rs & 1) * 8;
            sm1[row] = m1v[rs]; sk1[row] = k1i[rs]; sm2[row] = m2v[rs];
        }
    }
    __syncthreads();
    if (warp_n == 1 && (lane & 3) == 0) {
        #pragma unroll
        for (int rs = 0; rs < 4; ++rs) {
            int row = warp_m * 32 + (rs >> 1) * 16 + (lane >> 2) + (rs & 1) * 8;
            float a1 = sm1[row]; int ak = sk1[row]; float a2 = sm2[row];
            float nm2 = fminf(fminf(a2, m2v[rs]), fmaxf(a1, m1v[rs]));
            float nm1 = a1; int nk = ak;
            if (m1v[rs] < a1 || (m1v[rs] == a1 && k1i[rs] < ak)) { nm1 = m1v[rs]; nk = k1i[rs]; }
            sm1[row] = nm1; sk1[row] = nk; sm2[row] = nm2;
        }
    }
    __syncthreads();

    // ---- per-row finalize ----
    const bool full = (out_size >= BB * DD + 1 + BB);
    float lsum = 0.0f;
    if (tid < BM) {
        float v1 = sm1[tid], v2 = sm2[tid];
        int   kk = sk1[tid];
        float b1 = cs[kk] * G;
        if (full) out[(size_t)BB * DD + 1 + b0 + tid] = (float)kk;
        float est = -2.0f * (v1 + b1) / qs[kk];
        if (v2 <= v1 + 2.05f * b1 + 1e-4f && full) {
            int pos = atomicAdd(&g_nflag, 1);
            if (pos < FCAP) { g_flags[pos] = b0 + tid; g_fest[pos] = est; }
        }
        lsum = est;
    }
    #pragma unroll
    for (int o = 16; o > 0; o >>= 1) lsum += __shfl_xor_sync(0xffffffffu, lsum, o);
    __syncthreads();
    if (wid < 4 && lane == 0) red[wid] = lsum;
    __syncthreads();
    if (tid == 0) atomicAdd(&g_loss, red[0] + red[1] + red[2] + red[3]);

    // ---- gather z_embed ----
    {
        int r = tid >> 1, hf = tid & 1;
        int idx = sk1[r];
        const float4* Eq = (const float4*)(E + (size_t)idx * DD) + hf * 16;
        float4* Oq = (float4*)(out + (size_t)(b0 + r) * DD) + hf * 16;
        #pragma unroll
        for (int j = 0; j < 16; ++j) Oq[j] = Eq[j];
    }
}

// ---------------------------------------------------------------------------
// fix: exact fp32 argmin for flagged rows, one block per row (parallel).
// ---------------------------------------------------------------------------
__global__ void vq_fix(const float* __restrict__ X, const float* __restrict__ E,
                       float* __restrict__ out, int out_size) {
    if (out_size < BB * DD + 1 + BB) return;
    __shared__ float xs[DD];
    __shared__ float bv[256];
    __shared__ int   bi[256];
    int n = g_nflag;
    if (n > FCAP) n = FCAP;
    for (int i = blockIdx.x; i < n; i += gridDim.x) {
        int row = g_flags[i];
        if (threadIdx.x < DD) xs[threadIdx.x] = X[(size_t)row * DD + threadIdx.x];
        __syncthreads();
        float h = 0.0f;
        #pragma unroll 8
        for (int d = 0; d < DD; ++d) h = fmaf(xs[d], xs[d], h);
        h = -0.5f * h;
        float best = 3.4e38f; int bk = 0;
        #pragma unroll
        for (int j = 0; j < 4; ++j) {
            int k = threadIdx.x * 4 + j;
            const float* e = E + (size_t)k * DD;
            float dot = 0.0f;
            #pragma unroll 8
            for (int d = 0; d < DD; ++d) dot = fmaf(xs[d], e[d], dot);
            float v = g_p[k] + g_q[k] * (dot + h);
            if (v < best) { best = v; bk = k; }
        }
        bv[threadIdx.x] = best; bi[threadIdx.x] = bk;
        __syncthreads();
        for (int s = 128; s > 0; s >>= 1) {
            if (threadIdx.x < s) {
                float ov = bv[threadIdx.x + s]; int oi = bi[threadIdx.x + s];
                if (ov < bv[threadIdx.x] ||
                    (ov == bv[threadIdx.x] && oi < bi[threadIdx.x])) {
                    bv[threadIdx.x] = ov; bi[threadIdx.x] = oi;
                }
            }
            __syncthreads();
        }
        int kb = bi[0];
        if (threadIdx.x == 0) {
            out[(size_t)BB * DD + 1 + row] = (float)kb;
            float dexact = -2.0f * bv[0] / g_q[kb];
            atomicAdd(&g_loss, dexact - g_fest[i]);
        }
        if (threadIdx.x < 32) {
            float4 v = ((const float4*)(E + (size_t)kb * DD))[threadIdx.x];
            ((float4*)(out + (size_t)row * DD))[threadIdx.x] = v;
        }
        __syncthreads();
    }
}

__global__ void vq_fin(float* __restrict__ out, int out_size) {
    if (out_size >= BB * DD + 1)
        out[BB * DD] = 0.25f * g_loss / (float)((size_t)BB * DD);
}

extern "C" void kernel_launch(void* const* d_in, const int* in_sizes, int n_in,
                              void* d_out, int out_size) {
    const float* X = (const float*)d_in[0];
    const float* E = (const float*)d_in[1];
    const float* S = (const float*)d_in[2];
    float* out = (float*)d_out;

    cudaFuncSetAttribute(vq_main, cudaFuncAttributeMaxDynamicSharedMemorySize, SMEM_BYTES);

    vq_prep<<<KK / 8, 256>>>(E, S);
    vq_main<<<BB / BM, 256, SMEM_BYTES>>>(X, E, out, out_size);
    vq_fix<<<512, 256>>>(X, E, out, out_size);
    vq_fin<<<1, 1>>>(out, out_size);
}

// round 7
// speedup vs baseline: 12.1141x; 1.0550x over previous
#include <cuda_runtime.h>
#include <cuda_fp16.h>
#include <cstdint>

// ---------------------------------------------------------------------------
// VQ-VAE EMA quantizer: fp16 mma.sync (m16n8k16) + certified interval argmin.
//   acc initialized with h_r  ->  MMA produces dot + h directly.
//   lo_k = p''_k + q_k*acc, p''_k = p_k - c_k G + BIAS  (biased lower bound)
//   keys = (float_bits(lo) & ~1023) | k  -> integer top-2 min w/ index packed.
//   If key-m2 > key-m1 + slack -> argmin certified; else exact fix in vq_fix.
// ---------------------------------------------------------------------------

#define BB 131072
#define DD 128
#define KK 1024
#define BM 128
#define BN 64
#define NITER (KK/BN)   // 16
#define FCAP 16384
#define CBOUND 1.05e-3f
#define BIAS 2.0f

// smem byte offsets (per CTA; 2 CTAs/SM)
#define SM_A    0         // 32KB x fp16, A-frag permuted (+kc XOR swizzle)
#define SM_B    32768     // 2 stages x 16KB e fp16 B-frag permuted
#define SM_P    65536     // 4KB p''_k = p_k - c_k*G + BIAS
#define SM_Q    69632     // 4KB q_k
#define SM_C    73728     // 4KB c_k
#define SM_XX   77824     // 512B h_r
#define SM_M1   78336     // 512B packed int
#define SM_M2   78848     // 512B packed int
#define SM_RED  79360     // 64B
#define SMEM_BYTES 79424

__device__ float g_loss;
__device__ int   g_nflag;
__device__ int   g_done;
__device__ int   g_flags[FCAP];
__device__ float g_fest[FCAP];
__device__ float g_p[KK];
__device__ float g_q[KK];
__device__ float g_c[KK];
__device__ uint32_t g_eb[KK * DD / 2];   // B-frag permuted fp16 codebook

__device__ __forceinline__ void mma_h(float c[4], const uint4& a, uint32_t b0, uint32_t b1) {
    asm volatile(
        "mma.sync.aligned.m16n8k16.row.col.f32.f16.f16.f32 "
        "{%0,%1,%2,%3},{%4,%5,%6,%7},{%8,%9},{%0,%1,%2,%3};"
        : "+f"(c[0]), "+f"(c[1]), "+f"(c[2]), "+f"(c[3])
        : "r"(a.x), "r"(a.y), "r"(a.z), "r"(a.w), "r"(b0), "r"(b1));
}
__device__ __forceinline__ void cp16(uint32_t dst_smem, const void* src) {
    asm volatile("cp.async.cg.shared.global [%0], [%1], 16;"
                 :: "r"(dst_smem), "l"(src) : "memory");
}
__device__ __forceinline__ uint32_t smem_u32(const void* p) {
    uint32_t a;
    asm("{ .reg .u64 t; cvta.to.shared.u64 t, %1; cvt.u32.u64 %0, t; }"
        : "=r"(a) : "l"(p));
    return a;
}
__device__ __forceinline__ uint32_t h2pack(float lo, float hi) {
    __half2 h = __halves2half2(__float2half_rn(lo), __float2half_rn(hi));
    return *(uint32_t*)&h;
}
// key = (bits(lo) & ~0x3FF) | k  ; lo > 0 guaranteed -> int order == float order
__device__ __forceinline__ int mkkey(float lo, int k) {
    return (__float_as_int(lo) & 0xFFFFFC00) | k;
}

// ---------------------------------------------------------------------------
// prep: fp16 codebook in B-frag layout (64-codeword tiles), p/q/c, resets.
// ---------------------------------------------------------------------------
__global__ void vq_prep(const float* __restrict__ E, const float* __restrict__ S) {
    int wid = threadIdx.x >> 5, lane = threadIdx.x & 31;
    int k = blockIdx.x * 8 + wid;
    float4 v = ((const float4*)(E + (size_t)k * DD))[lane];
    float s2 = v.x * v.x + v.y * v.y + v.z * v.z + v.w * v.w;
    #pragma unroll
    for (int o = 16; o > 0; o >>= 1) s2 += __shfl_xor_sync(0xffffffffu, s2, o);

    int t = k >> 6, n = k & 63;
    int ng = n >> 4, blocksel = (n >> 3) & 1, g = n & 7;
    float e[4] = {v.x, v.y, v.z, v.w};
    #pragma unroll
    for (int j2 = 0; j2 < 2; ++j2) {
        int d0 = 4 * lane + 2 * j2;
        int kc = d0 >> 4;
        int tl = (d0 & 7) >> 1;
        int khi = (d0 >> 3) & 1;
        uint32_t h = h2pack(e[2 * j2], e[2 * j2 + 1]);
        g_eb[(size_t)t * 4096 +
             (size_t)((kc * 4 + ng) * 32 + g * 4 + tl) * 4 + blocksel * 2 + khi] = h;
    }
    if (lane == 0) {
        float s = S[k];
        g_p[k] = s * s2;
        g_q[k] = -2.0f * s;
        g_c[k] = CBOUND * s * sqrtf(s2);
    }
    if (blockIdx.x == 0 && threadIdx.x == 0) { g_loss = 0.0f; g_nflag = 0; g_done = 0; }
}

// ---------------------------------------------------------------------------
// main: 128 rows/CTA vs full codebook; BN=64/iter; warps 4M x 2N.
// ---------------------------------------------------------------------------
__global__ __launch_bounds__(256, 2) void vq_main(
    const float* __restrict__ X, const float* __restrict__ E,
    float* __restrict__ out, int out_size)
{
    extern __shared__ char smem[];
    const uint32_t sb = smem_u32(smem);
    const int tid    = threadIdx.x;
    const int lane   = tid & 31;
    const int wid    = tid >> 5;
    const int warp_m = wid >> 1;
    const int warp_n = wid & 1;
    const int b0     = blockIdx.x * BM;

    float* ps  = (float*)(smem + SM_P);
    float* qs  = (float*)(smem + SM_Q);
    float* cs  = (float*)(smem + SM_C);
    float* xx  = (float*)(smem + SM_XX);
    float* red = (float*)(smem + SM_RED);

    // B tile 0 fetch starts immediately
    {
        uint32_t dh = sb + SM_B + tid * 16;
        const char* src = (const char*)g_eb + tid * 16;
        #pragma unroll
        for (int r = 0; r < 4; ++r) cp16(dh + r * 4096, src + r * 4096);
        asm volatile("cp.async.commit_group;" ::: "memory");
    }

    // ---- X tile: load, fp16-round into A-frag layout (kc-XOR swizzle), norms, G ----
    float gmax = 0.0f;
    {
        const float4* Xg = (const float4*)(X + (size_t)b0 * DD);
        uint32_t* A32 = (uint32_t*)(smem + SM_A);
        #pragma unroll
        for (int it = 0; it < 16; ++it) {
            int idx = tid + it * 256;
            int r = idx >> 5;          // uniform per warp
            float4 v = Xg[r * 32 + lane];
            float n = v.x * v.x + v.y * v.y + v.z * v.z + v.w * v.w;
            #pragma unroll
            for (int o = 16; o > 0; o >>= 1) n += __shfl_xor_sync(0xffffffffu, n, o);
            if (lane == 0) xx[r] = -0.5f * n;
            gmax = fmaxf(gmax, n);
            int mtb = r >> 4, g = r & 7, rhigh = (r >> 3) & 1;
            int kc  = lane >> 2;
            int tl  = 2 * (lane & 1);
            int khi = (lane >> 1) & 1;
            int reg = rhigh + 2 * khi;
            int base = (kc * 8 + mtb) * 32;
            A32[(base + ((g * 4 + tl) ^ kc)) * 4 + reg]     = h2pack(v.x, v.y);
            A32[(base + ((g * 4 + tl + 1) ^ kc)) * 4 + reg] = h2pack(v.z, v.w);
        }
    }
    if (lane == 0) red[wid] = gmax;
    __syncthreads();
    float G;
    {
        float g = red[0];
        #pragma unroll
        for (int w = 1; w < 8; ++w) g = fmaxf(g, red[w]);
        G = sqrtf(g) * 1.0001f;
    }
    #pragma unroll
    for (int j = 0; j < 4; ++j) {
        int k = tid + 256 * j;
        float c = g_c[k];
        ps[k] = g_p[k] - c * G + BIAS;
        qs[k] = g_q[k];
        cs[k] = c;
    }
    asm volatile("cp.async.wait_group 0;" ::: "memory");
    __syncthreads();

    // h per row-slot (rs = mt*2+pr): row = warp_m*32 + mt*16 + (lane>>2) + 8*pr
    float hrow[4];
    #pragma unroll
    for (int mt = 0; mt < 2; ++mt)
        #pragma unroll
        for (int pr = 0; pr < 2; ++pr)
            hrow[mt * 2 + pr] = xx[warp_m * 32 + mt * 16 + (lane >> 2) + 8 * pr];

    int m1v[4] = {0x7FFFFFFF, 0x7FFFFFFF, 0x7FFFFFFF, 0x7FFFFFFF};
    int m2v[4] = {0x7FFFFFFF, 0x7FFFFFFF, 0x7FFFFFFF, 0x7FFFFFFF};

    const uint4* A4 = (const uint4*)(smem + SM_A);

    // resident A frags for kc 0..3 (half of K) -> halves A-LDS in mainloop
    uint4 areg[4][2];
    #pragma unroll
    for (int kc = 0; kc < 4; ++kc) {
        int ls = lane ^ kc;
        areg[kc][0] = A4[(kc * 8 + warp_m * 2) * 32 + ls];
        areg[kc][1] = A4[(kc * 8 + warp_m * 2 + 1) * 32 + ls];
    }

    const int klane = (lane & 3) << 1;

    for (int t = 0; t < NITER; ++t) {
        const int stage = t & 1;
        if (t + 1 < NITER) {
            uint32_t dh = sb + SM_B + (stage ^ 1) * 16384 + tid * 16;
            const char* src = (const char*)g_eb + (size_t)(t + 1) * 16384 + tid * 16;
            #pragma unroll
            for (int r = 0; r < 4; ++r) cp16(dh + r * 4096, src + r * 4096);
            asm volatile("cp.async.commit_group;" ::: "memory");
        }

        const uint4* B4 = (const uint4*)(smem + SM_B + stage * 16384);

        // acc initialized with h -> MMA yields dot + h
        float acc[2][4][4];
        #pragma unroll
        for (int mt = 0; mt < 2; ++mt)
            #pragma unroll
            for (int nb = 0; nb < 4; ++nb) {
                acc[mt][nb][0] = hrow[mt * 2];
                acc[mt][nb][1] = hrow[mt * 2];
                acc[mt][nb][2] = hrow[mt * 2 + 1];
                acc[mt][nb][3] = hrow[mt * 2 + 1];
            }

        uint4 a0 = areg[0][0], a1 = areg[0][1];
        uint4 bb0 = B4[(warp_n * 2) * 32 + lane];
        uint4 bb1 = B4[(warp_n * 2 + 1) * 32 + lane];
        #pragma unroll
        for (int kc = 0; kc < 8; ++kc) {
            uint4 a0n, a1n, b0n, b1n;
            if (kc < 7) {
                int kn = kc + 1;
                b0n = B4[(kn * 4 + warp_n * 2) * 32 + lane];
                b1n = B4[(kn * 4 + warp_n * 2 + 1) * 32 + lane];
                if (kn < 4) {
                    a0n = areg[kn][0]; a1n = areg[kn][1];
                } else {
                    int ls = lane ^ kn;
                    a0n = A4[(kn * 8 + warp_m * 2) * 32 + ls];
                    a1n = A4[(kn * 8 + warp_m * 2 + 1) * 32 + ls];
                }
            }
            mma_h(acc[0][0], a0, bb0.x, bb0.y);
            mma_h(acc[0][1], a0, bb0.z, bb0.w);
            mma_h(acc[0][2], a0, bb1.x, bb1.y);
            mma_h(acc[0][3], a0, bb1.z, bb1.w);
            mma_h(acc[1][0], a1, bb0.x, bb0.y);
            mma_h(acc[1][1], a1, bb0.z, bb0.w);
            mma_h(acc[1][2], a1, bb1.x, bb1.y);
            mma_h(acc[1][3], a1, bb1.z, bb1.w);
            if (kc < 7) { a0 = a0n; a1 = a1n; bb0 = b0n; bb1 = b1n; }
        }

        // epilogue: packed-key certified lower bounds, top-2 integer min
        #pragma unroll
        for (int ntg = 0; ntg < 2; ++ntg) {
            #pragma unroll
            for (int blk = 0; blk < 2; ++blk) {
                int nb = ntg * 2 + blk;
                int k0 = t * 64 + (warp_n * 2 + ntg) * 16 + blk * 8 + klane;
                float2 pp = *(const float2*)(ps + k0);
                float2 qq = *(const float2*)(qs + k0);
                #pragma unroll
                for (int mt = 0; mt < 2; ++mt) {
                    #pragma unroll
                    for (int pr = 0; pr < 2; ++pr) {
                        int rs = mt * 2 + pr;
                        int key0 = mkkey(fmaf(qq.x, acc[mt][nb][pr * 2 + 0], pp.x), k0);
                        int key1 = mkkey(fmaf(qq.y, acc[mt][nb][pr * 2 + 1], pp.y), k0 + 1);
                        m2v[rs] = min(m2v[rs], max(m1v[rs], key0));
                        m1v[rs] = min(m1v[rs], key0);
                        m2v[rs] = min(m2v[rs], max(m1v[rs], key1));
                        m1v[rs] = min(m1v[rs], key1);
                    }
                }
            }
        }

        asm volatile("cp.async.wait_group 0;" ::: "memory");
        __syncthreads();
    }

    // ---- reduce: lanes sharing rows (xor 1,2), then warp_n pair via smem ----
    #pragma unroll
    for (int o = 1; o <= 2; o <<= 1) {
        #pragma unroll
        for (int rs = 0; rs < 4; ++rs) {
            int om1 = __shfl_xor_sync(0xffffffffu, m1v[rs], o);
            int om2 = __shfl_xor_sync(0xffffffffu, m2v[rs], o);
            m2v[rs] = min(min(m2v[rs], om2), max(m1v[rs], om1));
            m1v[rs] = min(m1v[rs], om1);
        }
    }
    int* sm1 = (int*)(smem + SM_M1);
    int* sm2 = (int*)(smem + SM_M2);
    if (warp_n == 0 && (lane & 3) == 0) {
        #pragma unroll
        for (int rs = 0; rs < 4; ++rs) {
            int row = warp_m * 32 + (rs >> 1) * 16 + (lane >> 2) + (rs & 1) * 8;
            sm1[row] = m1v[rs]; sm2[row] = m2v[rs];
        }
    }
    __syncthreads();
    if (warp_n == 1 && (lane & 3) == 0) {
        #pragma unroll
        for (int rs = 0; rs < 4; ++rs) {
            int row = warp_m * 32 + (rs >> 1) * 16 + (lane >> 2) + (rs & 1) * 8;
            int a1 = sm1[row], a2 = sm2[row];
            sm2[row] = min(min(a2, m2v[rs]), max(a1, m1v[rs]));
            sm1[row] = min(a1, m1v[rs]);
        }
    }
    __syncthreads();

    // ---- per-row finalize ----
    const bool full = (out_size >= BB * DD + 1 + BB);
    float lsum = 0.0f;
    if (tid < BM) {
        int pm1 = sm1[tid], pm2 = sm2[tid];
        int kk = pm1 & 1023;
        float v1 = __int_as_float(pm1 & 0xFFFFFC00) - BIAS;
        float v2 = __int_as_float(pm2 & 0xFFFFFC00) - BIAS;
        float b1 = cs[kk] * G;
        if (full) out[(size_t)BB * DD + 1 + b0 + tid] = (float)kk;
        float est = -2.0f * (v1 + b1) / qs[kk];
        float slack = 2.05f * b1 + 3e-4f * (v1 + BIAS) + 1e-4f;
        if (v2 <= v1 + slack && full) {
            int pos = atomicAdd(&g_nflag, 1);
            if (pos < FCAP) { g_flags[pos] = b0 + tid; g_fest[pos] = est; }
        }
        lsum = est;
    }
    #pragma unroll
    for (int o = 16; o > 0; o >>= 1) lsum += __shfl_xor_sync(0xffffffffu, lsum, o);
    __syncthreads();
    if (wid < 4 && lane == 0) red[wid] = lsum;
    __syncthreads();
    if (tid == 0) atomicAdd(&g_loss, red[0] + red[1] + red[2] + red[3]);

    // ---- gather z_embed ----
    {
        int r = tid >> 1, hf = tid & 1;
        int idx = sm1[r] & 1023;
        const float4* Eq = (const float4*)(E + (size_t)idx * DD) + hf * 16;
        float4* Oq = (float4*)(out + (size_t)(b0 + r) * DD) + hf * 16;
        #pragma unroll
        for (int j = 0; j < 16; ++j) Oq[j] = Eq[j];
    }
}

// ---------------------------------------------------------------------------
// fix: exact fp32 argmin for flagged rows (parallel) + final loss write.
// ---------------------------------------------------------------------------
__global__ void vq_fix(const float* __restrict__ X, const float* __restrict__ E,
                       float* __restrict__ out, int out_size) {
    __shared__ float xs[DD];
    __shared__ float bv[256];
    __shared__ int   bi[256];
    int n = 0;
    if (out_size >= BB * DD + 1 + BB) {
        n = g_nflag;
        if (n > FCAP) n = FCAP;
    }
    for (int i = blockIdx.x; i < n; i += gridDim.x) {
        int row = g_flags[i];
        if (threadIdx.x < DD) xs[threadIdx.x] = X[(size_t)row * DD + threadIdx.x];
        __syncthreads();
        float h = 0.0f;
        #pragma unroll 8
        for (int d = 0; d < DD; ++d) h = fmaf(xs[d], xs[d], h);
        h = -0.5f * h;
        float best = 3.4e38f; int bk = 0;
        #pragma unroll
        for (int j = 0; j < 4; ++j) {
            int k = threadIdx.x * 4 + j;
            const float* e = E + (size_t)k * DD;
            float dot = 0.0f;
            #pragma unroll 8
            for (int d = 0; d < DD; ++d) dot = fmaf(xs[d], e[d], dot);
            float v = g_p[k] + g_q[k] * (dot + h);
            if (v < best) { best = v; bk = k; }
        }
        bv[threadIdx.x] = best; bi[threadIdx.x] = bk;
        __syncthreads();
        for (int s = 128; s > 0; s >>= 1) {
            if (threadIdx.x < s) {
                float ov = bv[threadIdx.x + s]; int oi = bi[threadIdx.x + s];
                if (ov < bv[threadIdx.x] ||
                    (ov == bv[threadIdx.x] && oi < bi[threadIdx.x])) {
                    bv[threadIdx.x] = ov; bi[threadIdx.x] = oi;
                }
            }
            __syncthreads();
        }
        int kb = bi[0];
        if (threadIdx.x == 0) {
            out[(size_t)BB * DD + 1 + row] = (float)kb;
            float dexact = -2.0f * bv[0] / g_q[kb];
            atomicAdd(&g_loss, dexact - g_fest[i]);
        }
        if (threadIdx.x < 32) {
            float4 v = ((const float4*)(E + (size_t)kb * DD))[threadIdx.x];
            ((float4*)(out + (size_t)row * DD))[threadIdx.x] = v;
        }
        __syncthreads();
    }
    // last block to finish writes the final loss scalar (fin merged here)
    __syncthreads();
    if (threadIdx.x == 0) {
        __threadfence();
        int d = atomicAdd(&g_done, 1);
        if (d == (int)gridDim.x - 1 && out_size >= BB * DD + 1) {
            out[(size_t)BB * DD] = 0.25f * g_loss / (float)((size_t)BB * DD);
        }
    }
}

extern "C" void kernel_launch(void* const* d_in, const int* in_sizes, int n_in,
                              void* d_out, int out_size) {
    const float* X = (const float*)d_in[0];
    const float* E = (const float*)d_in[1];
    const float* S = (const float*)d_in[2];
    float* out = (float*)d_out;

    cudaFuncSetAttribute(vq_main, cudaFuncAttributeMaxDynamicSharedMemorySize, SMEM_BYTES);

    vq_prep<<<KK / 8, 256>>>(E, S);
    vq_main<<<BB / BM, 256, SMEM_BYTES>>>(X, E, out, out_size);
    vq_fix<<<512, 256>>>(X, E, out, out_size);
}